// round 4
// baseline (speedup 1.0000x reference)
#include <cuda_runtime.h>
#include <math.h>

#define D 1024
#define S 128
#define DECAY 0.99f
#define INHIB 1.5f
#define TOPK 51
#define GROUP 8

// Scratch (static device globals — no allocation).
__device__ float g_sbuf[S * D];    // sparsified token vectors [S][D]
__device__ float g_expect[S * D];  // expectation_t[j] accumulated by scan atomics
__device__ int   g_flag[S];        // token-ready flags (reset by finalize each launch)

// Coherent (L2) load helpers — g_sbuf is produced DURING the kernel, so the
// non-coherent __ldg path is illegal for it. ld.global.cg snoops L2, which is
// the coherence point for the producers' plain stores.
__device__ __forceinline__ float4 ldcg4(const float* p) {
    return __ldcg(reinterpret_cast<const float4*>(p));
}

// ---------------------------------------------------------------------------
// Fused kernel: grid = 256 blocks x 256 threads.
//  Producer role (blocks 0..127, warp 0): exact radix top-k sparsify of token
//  `bid`, zero g_expect row, __threadfence, atomicExch flag (release).
//  Producers never wait on anyone and are wave-1 resident => no deadlock.
//  Consumer role (all blocks): register-resident elementwise scan
//     v[i,j] <- relu(DECAY*v + s_t[i]*s_t[j]*g_t)
//  streaming every snapshot to its output slice. Handshake per 8-step group:
//  thread 0 volatile-polls flags, then __threadfence (acquire) + __syncthreads
//  orders all threads' subsequent g_sbuf loads after producer stores.
//  Expectation for drift accumulates into g_expect[t+1] via atomics (guarded:
//  only when this block's 4 s-rows are nonzero, ~19% of steps).
// ---------------------------------------------------------------------------
__global__ void __launch_bounds__(256, 2) fused_kernel(
    const float* __restrict__ emb, const float* __restrict__ con,
    float* __restrict__ states) {
    const int tid = threadIdx.x;
    const int bid = blockIdx.x;
    const int i0 = bid * 4;
    const int j = tid * 4;

    // ---------------- producer: warp 0 of blocks 0..127 ----------------
    if (bid < S && tid < 32) {
        const int t = bid;
        const int lane = tid;

        // zero g_expect row t (must precede flag so consumers' atomics are safe)
        {
            float4 z = make_float4(0.f, 0.f, 0.f, 0.f);
            float4* e4 = reinterpret_cast<float4*>(g_expect + (size_t)t * D);
#pragma unroll
            for (int c = 0; c < 8; ++c) e4[c * 32 + lane] = z;
        }

        // load relu(x) as raw bits (nonneg-float order == uint order)
        unsigned pb[32];
        const float4* row = reinterpret_cast<const float4*>(emb + (size_t)t * D);
#pragma unroll
        for (int c = 0; c < 8; ++c) {
            float4 x = row[c * 32 + lane];
            pb[c * 4 + 0] = __float_as_uint(fmaxf(x.x, 0.f));
            pb[c * 4 + 1] = __float_as_uint(fmaxf(x.y, 0.f));
            pb[c * 4 + 2] = __float_as_uint(fmaxf(x.z, 0.f));
            pb[c * 4 + 3] = __float_as_uint(fmaxf(x.w, 0.f));
        }

        // exact bitwise radix select: max T with count(bits >= T) >= TOPK
        unsigned thr = 0u;
        for (int b = 30; b >= 0; --b) {
            unsigned cand = thr | (1u << b);
            int c = 0;
#pragma unroll
            for (int k = 0; k < 32; ++k) c += (pb[k] >= cand) ? 1 : 0;
            c = __reduce_add_sync(0xffffffffu, c);
            if (c >= TOPK) thr = cand;
        }

        float4* out = reinterpret_cast<float4*>(g_sbuf + (size_t)t * D);
#pragma unroll
        for (int c = 0; c < 8; ++c) {
            float4 sv;
            sv.x = (pb[c * 4 + 0] >= thr) ? __uint_as_float(pb[c * 4 + 0]) : 0.f;
            sv.y = (pb[c * 4 + 1] >= thr) ? __uint_as_float(pb[c * 4 + 1]) : 0.f;
            sv.z = (pb[c * 4 + 2] >= thr) ? __uint_as_float(pb[c * 4 + 2]) : 0.f;
            sv.w = (pb[c * 4 + 3] >= thr) ? __uint_as_float(pb[c * 4 + 3]) : 0.f;
            out[c * 32 + lane] = sv;
        }

        __threadfence();   // release: all stores above visible before flag
        __syncwarp();
        if (lane == 0) atomicExch(&g_flag[t], 1);
    }

    // ---------------- consumer: all blocks, all threads ----------------
    float4 v[4];
#pragma unroll
    for (int r = 0; r < 4; ++r) v[r] = make_float4(0.f, 0.f, 0.f, 0.f);

    float4 sj = make_float4(0.f, 0.f, 0.f, 0.f);   // s_t[j..j+3]
    float4 si = make_float4(0.f, 0.f, 0.f, 0.f);   // s_t[i0..i0+3] (block-uniform)

    for (int ts = 0; ts < S; ts += GROUP) {
        // Wait for tokens [ts .. min(ts+GROUP, S-1)] (covers prefetch targets).
        if (tid == 0) {
            int hi = ts + GROUP;
            if (hi > S - 1) hi = S - 1;
            for (int u = ts; u <= hi; ++u) {
                while (((volatile int*)g_flag)[u] == 0) __nanosleep(64);
            }
            __threadfence();  // acquire: order subsequent loads after flag
        }
        __syncthreads();      // broadcast the acquire to the whole block

        if (ts == 0) {
            sj = ldcg4(g_sbuf + j);
            si = ldcg4(g_sbuf + i0);
        }

#pragma unroll
        for (int tt = 0; tt < GROUP; ++tt) {
            const int t = ts + tt;
            float4 sjn = sj, sin = si;
            if (t + 1 < S) {
                sjn = ldcg4(g_sbuf + (size_t)(t + 1) * D + j);
                sin = ldcg4(g_sbuf + (size_t)(t + 1) * D + i0);
            }
            const float g = 1.0f - __ldg(con + t) * INHIB;
            const float a0 = si.x * g, a1 = si.y * g, a2 = si.z * g, a3 = si.w * g;
            float* o = states + (size_t)t * D * D + j;

            v[0].x = fmaxf(fmaf(a0, sj.x, DECAY * v[0].x), 0.f);
            v[0].y = fmaxf(fmaf(a0, sj.y, DECAY * v[0].y), 0.f);
            v[0].z = fmaxf(fmaf(a0, sj.z, DECAY * v[0].z), 0.f);
            v[0].w = fmaxf(fmaf(a0, sj.w, DECAY * v[0].w), 0.f);
            v[1].x = fmaxf(fmaf(a1, sj.x, DECAY * v[1].x), 0.f);
            v[1].y = fmaxf(fmaf(a1, sj.y, DECAY * v[1].y), 0.f);
            v[1].z = fmaxf(fmaf(a1, sj.z, DECAY * v[1].z), 0.f);
            v[1].w = fmaxf(fmaf(a1, sj.w, DECAY * v[1].w), 0.f);
            v[2].x = fmaxf(fmaf(a2, sj.x, DECAY * v[2].x), 0.f);
            v[2].y = fmaxf(fmaf(a2, sj.y, DECAY * v[2].y), 0.f);
            v[2].z = fmaxf(fmaf(a2, sj.z, DECAY * v[2].z), 0.f);
            v[2].w = fmaxf(fmaf(a2, sj.w, DECAY * v[2].w), 0.f);
            v[3].x = fmaxf(fmaf(a3, sj.x, DECAY * v[3].x), 0.f);
            v[3].y = fmaxf(fmaf(a3, sj.y, DECAY * v[3].y), 0.f);
            v[3].z = fmaxf(fmaf(a3, sj.z, DECAY * v[3].z), 0.f);
            v[3].w = fmaxf(fmaf(a3, sj.w, DECAY * v[3].w), 0.f);

            __stcs(reinterpret_cast<float4*>(o + (size_t)(i0 + 0) * D), v[0]);
            __stcs(reinterpret_cast<float4*>(o + (size_t)(i0 + 1) * D), v[1]);
            __stcs(reinterpret_cast<float4*>(o + (size_t)(i0 + 2) * D), v[2]);
            __stcs(reinterpret_cast<float4*>(o + (size_t)(i0 + 3) * D), v[3]);

            // Fused expectation: s_{t+1}[i0+r] * v[r][.] -> g_expect[t+1]
            if (t + 1 < S) {
                if (sin.x != 0.f || sin.y != 0.f || sin.z != 0.f || sin.w != 0.f) {
                    float4 cacc;
                    cacc.x = sin.x * v[0].x + sin.y * v[1].x + sin.z * v[2].x + sin.w * v[3].x;
                    cacc.y = sin.x * v[0].y + sin.y * v[1].y + sin.z * v[2].y + sin.w * v[3].y;
                    cacc.z = sin.x * v[0].z + sin.y * v[1].z + sin.z * v[2].z + sin.w * v[3].z;
                    cacc.w = sin.x * v[0].w + sin.y * v[1].w + sin.z * v[2].w + sin.w * v[3].w;
                    float* e = g_expect + (size_t)(t + 1) * D + j;
                    atomicAdd(e + 0, cacc.x);
                    atomicAdd(e + 1, cacc.y);
                    atomicAdd(e + 2, cacc.z);
                    atomicAdd(e + 3, cacc.w);
                }
            }
            sj = sjn;
            si = sin;
        }
    }
}

// ---------------------------------------------------------------------------
// Finalize: drift_t = ||s_t - expect_t||; also resets flags for the next
// launch/replay (deterministic steady state: flags are 0 on entry every call).
// ---------------------------------------------------------------------------
__global__ void __launch_bounds__(256) finalize_kernel(float* __restrict__ drifts) {
    const int t = blockIdx.x;
    const int tid = threadIdx.x;
    const int lane = tid & 31, wid = tid >> 5;

    float4 s4 = reinterpret_cast<const float4*>(g_sbuf + (size_t)t * D)[tid];
    float4 e4 = reinterpret_cast<const float4*>(g_expect + (size_t)t * D)[tid];
    const float dx = s4.x - e4.x, dy = s4.y - e4.y;
    const float dz = s4.z - e4.z, dw = s4.w - e4.w;
    float sum = dx * dx + dy * dy + dz * dz + dw * dw;
#pragma unroll
    for (int o = 16; o > 0; o >>= 1) sum += __shfl_xor_sync(0xffffffffu, sum, o);

    __shared__ float ws[8];
    if (lane == 0) ws[wid] = sum;
    __syncthreads();
    if (tid == 0) {
        float tot = 0.f;
        for (int w = 0; w < 8; ++w) tot += ws[w];
        drifts[t] = sqrtf(tot);
        g_flag[t] = 0;  // reset for next launch / graph replay
    }
}

// ---------------------------------------------------------------------------
extern "C" void kernel_launch(void* const* d_in, const int* in_sizes, int n_in,
                              void* d_out, int out_size) {
    const float* emb;
    const float* con;
    if (in_sizes[0] == S) {
        con = (const float*)d_in[0];
        emb = (const float*)d_in[1];
    } else {
        emb = (const float*)d_in[0];
        con = (const float*)d_in[1];
    }
    float* out = (float*)d_out;
    float* drifts = out;      // [S]
    float* states = out + S;  // [S, D, D]

    fused_kernel<<<D / 4, 256>>>(emb, con, states);
    finalize_kernel<<<S, 256>>>(drifts);
}

// round 5
// speedup vs baseline: 1.0330x; 1.0330x over previous
#include <cuda_runtime.h>
#include <math.h>

#define D 1024
#define S 128
#define DECAY 0.99f
#define INHIB 1.5f
#define TOPK 51
#define GROUP 8
#define NGROUPS (S / GROUP)

// Scratch (static device globals — no allocation).
__device__ float g_sbuf[S * D];    // sparsified token vectors [S][D]
__device__ float g_expect[S * D];  // expectation_t[j] accumulated by scan atomics
__device__ int   g_flag[S];        // token-ready flags (reset by finalize each launch)

// ---------------------------------------------------------------------------
// Fused kernel: grid = 256 blocks x 256 threads, >=2 blocks/SM.
//  Producers (blocks 0..127, warp 0): exact radix top-k sparsify of token bid,
//  zero g_expect row, __threadfence, atomicExch flag (release). Never wait.
//  Consumers (all blocks): per 8-step group, thread 0 polls flags + acquire
//  fence + __syncthreads, then ALL threads cooperatively stage the 8 token
//  rows into smem with coalesced ldcg (L2-coherent; g_sbuf is produced during
//  this kernel so the L1/RO path is off-limits). The scan inner loop touches
//  only smem + registers:
//     v[i,j] <- relu(DECAY*v + s_t[i]*s_t[j]*g_t)
//  streaming every snapshot straight out with __stcs. Expectation for drift
//  accumulates into g_expect[t+1] via guarded atomics; the tt==7 contribution
//  (needs s_{t+1} from the next group) is deferred to just after the next
//  staging, where v still holds state_t.
// ---------------------------------------------------------------------------
__global__ void __launch_bounds__(256, 2) fused_kernel(
    const float* __restrict__ emb, const float* __restrict__ con,
    float* __restrict__ states) {
    const int tid = threadIdx.x;
    const int bid = blockIdx.x;
    const int i0 = bid * 4;
    const int j = tid * 4;

    // ---------------- producer: warp 0 of blocks 0..127 ----------------
    if (bid < S && tid < 32) {
        const int t = bid;
        const int lane = tid;

        {   // zero g_expect row t (before flag: consumers' atomics need it)
            float4 z = make_float4(0.f, 0.f, 0.f, 0.f);
            float4* e4 = reinterpret_cast<float4*>(g_expect + (size_t)t * D);
#pragma unroll
            for (int c = 0; c < 8; ++c) e4[c * 32 + lane] = z;
        }

        unsigned pb[32];
        const float4* row = reinterpret_cast<const float4*>(emb + (size_t)t * D);
#pragma unroll
        for (int c = 0; c < 8; ++c) {
            float4 x = row[c * 32 + lane];
            pb[c * 4 + 0] = __float_as_uint(fmaxf(x.x, 0.f));
            pb[c * 4 + 1] = __float_as_uint(fmaxf(x.y, 0.f));
            pb[c * 4 + 2] = __float_as_uint(fmaxf(x.z, 0.f));
            pb[c * 4 + 3] = __float_as_uint(fmaxf(x.w, 0.f));
        }

        // exact bitwise radix select: max T with count(bits >= T) >= TOPK
        // (nonneg-float order == uint order)
        unsigned thr = 0u;
        for (int b = 30; b >= 0; --b) {
            unsigned cand = thr | (1u << b);
            int c = 0;
#pragma unroll
            for (int k = 0; k < 32; ++k) c += (pb[k] >= cand) ? 1 : 0;
            c = __reduce_add_sync(0xffffffffu, c);
            if (c >= TOPK) thr = cand;
        }

        float4* outp = reinterpret_cast<float4*>(g_sbuf + (size_t)t * D);
#pragma unroll
        for (int c = 0; c < 8; ++c) {
            float4 sv;
            sv.x = (pb[c * 4 + 0] >= thr) ? __uint_as_float(pb[c * 4 + 0]) : 0.f;
            sv.y = (pb[c * 4 + 1] >= thr) ? __uint_as_float(pb[c * 4 + 1]) : 0.f;
            sv.z = (pb[c * 4 + 2] >= thr) ? __uint_as_float(pb[c * 4 + 2]) : 0.f;
            sv.w = (pb[c * 4 + 3] >= thr) ? __uint_as_float(pb[c * 4 + 3]) : 0.f;
            outp[c * 32 + lane] = sv;
        }

        __threadfence();   // release: stores above visible before flag
        __syncwarp();
        if (lane == 0) atomicExch(&g_flag[t], 1);
    }

    // ---------------- consumer: all blocks, all threads ----------------
    __shared__ float4 rows[GROUP][256];   // staged s rows for this group (32KB)

    float4 v[4];
#pragma unroll
    for (int r = 0; r < 4; ++r) v[r] = make_float4(0.f, 0.f, 0.f, 0.f);

    for (int grp = 0; grp < NGROUPS; ++grp) {
        const int ts = grp * GROUP;

        // Wait for this group's tokens (acquire), then stage rows into smem.
        if (tid == 0) {
            for (int u = ts; u < ts + GROUP; ++u) {
                while (((volatile int*)g_flag)[u] == 0) __nanosleep(64);
            }
            __threadfence();  // acquire for the whole block (with the barrier)
        }
        __syncthreads();      // also separates prior group's smem reads

        // Coalesced ldcg staging: 2048 float4s, 8 per thread, MLP=8.
        {
            const float4* src = reinterpret_cast<const float4*>(g_sbuf + (size_t)ts * D);
#pragma unroll
            for (int k = 0; k < 8; ++k) {
                int f = tid + k * 256;            // [0, 2048)
                rows[f >> 8][f & 255] = __ldcg(src + f);
            }
        }
        __syncthreads();

        // Deferred expectation contribution from last step of previous group:
        // v == state_{ts-1}; s_ts is rows[0][bid].
        if (grp > 0) {
            const float4 sn = rows[0][bid];   // block-uniform broadcast
            if (sn.x != 0.f || sn.y != 0.f || sn.z != 0.f || sn.w != 0.f) {
                float4 cacc;
                cacc.x = sn.x * v[0].x + sn.y * v[1].x + sn.z * v[2].x + sn.w * v[3].x;
                cacc.y = sn.x * v[0].y + sn.y * v[1].y + sn.z * v[2].y + sn.w * v[3].y;
                cacc.z = sn.x * v[0].z + sn.y * v[1].z + sn.z * v[2].z + sn.w * v[3].z;
                cacc.w = sn.x * v[0].w + sn.y * v[1].w + sn.z * v[2].w + sn.w * v[3].w;
                float* e = g_expect + (size_t)ts * D + j;
                atomicAdd(e + 0, cacc.x);
                atomicAdd(e + 1, cacc.y);
                atomicAdd(e + 2, cacc.z);
                atomicAdd(e + 3, cacc.w);
            }
        }

#pragma unroll
        for (int tt = 0; tt < GROUP; ++tt) {
            const int t = ts + tt;
            const float4 sj = rows[tt][tid];
            const float4 si = rows[tt][bid];          // broadcast
            const float g = 1.0f - __ldg(con + t) * INHIB;
            const float a0 = si.x * g, a1 = si.y * g, a2 = si.z * g, a3 = si.w * g;
            float* o = states + (size_t)t * D * D + j;

            v[0].x = fmaxf(fmaf(a0, sj.x, DECAY * v[0].x), 0.f);
            v[0].y = fmaxf(fmaf(a0, sj.y, DECAY * v[0].y), 0.f);
            v[0].z = fmaxf(fmaf(a0, sj.z, DECAY * v[0].z), 0.f);
            v[0].w = fmaxf(fmaf(a0, sj.w, DECAY * v[0].w), 0.f);
            v[1].x = fmaxf(fmaf(a1, sj.x, DECAY * v[1].x), 0.f);
            v[1].y = fmaxf(fmaf(a1, sj.y, DECAY * v[1].y), 0.f);
            v[1].z = fmaxf(fmaf(a1, sj.z, DECAY * v[1].z), 0.f);
            v[1].w = fmaxf(fmaf(a1, sj.w, DECAY * v[1].w), 0.f);
            v[2].x = fmaxf(fmaf(a2, sj.x, DECAY * v[2].x), 0.f);
            v[2].y = fmaxf(fmaf(a2, sj.y, DECAY * v[2].y), 0.f);
            v[2].z = fmaxf(fmaf(a2, sj.z, DECAY * v[2].z), 0.f);
            v[2].w = fmaxf(fmaf(a2, sj.w, DECAY * v[2].w), 0.f);
            v[3].x = fmaxf(fmaf(a3, sj.x, DECAY * v[3].x), 0.f);
            v[3].y = fmaxf(fmaf(a3, sj.y, DECAY * v[3].y), 0.f);
            v[3].z = fmaxf(fmaf(a3, sj.z, DECAY * v[3].z), 0.f);
            v[3].w = fmaxf(fmaf(a3, sj.w, DECAY * v[3].w), 0.f);

            __stcs(reinterpret_cast<float4*>(o + (size_t)(i0 + 0) * D), v[0]);
            __stcs(reinterpret_cast<float4*>(o + (size_t)(i0 + 1) * D), v[1]);
            __stcs(reinterpret_cast<float4*>(o + (size_t)(i0 + 2) * D), v[2]);
            __stcs(reinterpret_cast<float4*>(o + (size_t)(i0 + 3) * D), v[3]);

            // Expectation contribution for t+1 (within-group case only).
            if (tt < GROUP - 1) {
                const float4 sn = rows[tt + 1][bid];  // broadcast
                if (sn.x != 0.f || sn.y != 0.f || sn.z != 0.f || sn.w != 0.f) {
                    float4 cacc;
                    cacc.x = sn.x * v[0].x + sn.y * v[1].x + sn.z * v[2].x + sn.w * v[3].x;
                    cacc.y = sn.x * v[0].y + sn.y * v[1].y + sn.z * v[2].y + sn.w * v[3].y;
                    cacc.z = sn.x * v[0].z + sn.y * v[1].z + sn.z * v[2].z + sn.w * v[3].z;
                    cacc.w = sn.x * v[0].w + sn.y * v[1].w + sn.z * v[2].w + sn.w * v[3].w;
                    float* e = g_expect + (size_t)(t + 1) * D + j;
                    atomicAdd(e + 0, cacc.x);
                    atomicAdd(e + 1, cacc.y);
                    atomicAdd(e + 2, cacc.z);
                    atomicAdd(e + 3, cacc.w);
                }
            }
        }
    }
}

// ---------------------------------------------------------------------------
// Finalize: drift_t = ||s_t - expect_t||; resets flags for the next replay.
// ---------------------------------------------------------------------------
__global__ void __launch_bounds__(256) finalize_kernel(float* __restrict__ drifts) {
    const int t = blockIdx.x;
    const int tid = threadIdx.x;
    const int lane = tid & 31, wid = tid >> 5;

    float4 s4 = reinterpret_cast<const float4*>(g_sbuf + (size_t)t * D)[tid];
    float4 e4 = reinterpret_cast<const float4*>(g_expect + (size_t)t * D)[tid];
    const float dx = s4.x - e4.x, dy = s4.y - e4.y;
    const float dz = s4.z - e4.z, dw = s4.w - e4.w;
    float sum = dx * dx + dy * dy + dz * dz + dw * dw;
#pragma unroll
    for (int o = 16; o > 0; o >>= 1) sum += __shfl_xor_sync(0xffffffffu, sum, o);

    __shared__ float ws[8];
    if (lane == 0) ws[wid] = sum;
    __syncthreads();
    if (tid == 0) {
        float tot = 0.f;
        for (int w = 0; w < 8; ++w) tot += ws[w];
        drifts[t] = sqrtf(tot);
        g_flag[t] = 0;  // reset for next launch / graph replay
    }
}

// ---------------------------------------------------------------------------
extern "C" void kernel_launch(void* const* d_in, const int* in_sizes, int n_in,
                              void* d_out, int out_size) {
    const float* emb;
    const float* con;
    if (in_sizes[0] == S) {
        con = (const float*)d_in[0];
        emb = (const float*)d_in[1];
    } else {
        emb = (const float*)d_in[0];
        con = (const float*)d_in[1];
    }
    float* out = (float*)d_out;
    float* drifts = out;      // [S]
    float* states = out + S;  // [S, D, D]

    fused_kernel<<<D / 4, 256>>>(emb, con, states);
    finalize_kernel<<<S, 256>>>(drifts);
}

// round 6
// speedup vs baseline: 1.2375x; 1.1980x over previous
#include <cuda_runtime.h>
#include <math.h>

#define D 1024
#define S 128
#define DECAY 0.99f
#define INHIB 1.5f
#define TOPK 51
#define SCAN_R 4

// Scratch (static device globals — no allocation).
__device__ float g_sbuf[S * D];    // sparsified token vectors [S][D]
__device__ float g_expect[S * D];  // expectation_t[j] accumulated by scan atomics

// ---------------------------------------------------------------------------
// Kernel 1: sparsify. 16 blocks x 256 threads; warp w of block b owns token
// t = b*8 + w. Exact radix top-k select (nonneg-float order == uint order),
// fully warp-local (no block barriers). Each warp also zeroes g_expect row t.
// ---------------------------------------------------------------------------
__global__ void __launch_bounds__(256) sparsify_kernel(const float* __restrict__ emb) {
    const int t = blockIdx.x * 8 + (threadIdx.x >> 5);
    const int lane = threadIdx.x & 31;

    // zero g_expect row t (scan's atomics accumulate into it)
    {
        float4 z = make_float4(0.f, 0.f, 0.f, 0.f);
        float4* e4 = reinterpret_cast<float4*>(g_expect + (size_t)t * D);
#pragma unroll
        for (int c = 0; c < 8; ++c) e4[c * 32 + lane] = z;
    }

    // load relu(x) as raw bits, 32 values per lane, coalesced float4 chunks
    unsigned pb[32];
    const float4* row = reinterpret_cast<const float4*>(emb + (size_t)t * D);
#pragma unroll
    for (int c = 0; c < 8; ++c) {
        float4 x = row[c * 32 + lane];
        pb[c * 4 + 0] = __float_as_uint(fmaxf(x.x, 0.f));
        pb[c * 4 + 1] = __float_as_uint(fmaxf(x.y, 0.f));
        pb[c * 4 + 2] = __float_as_uint(fmaxf(x.z, 0.f));
        pb[c * 4 + 3] = __float_as_uint(fmaxf(x.w, 0.f));
    }

    // exact bitwise radix select: max T with count(bits >= T) >= TOPK
    unsigned thr = 0u;
    for (int b = 30; b >= 0; --b) {
        unsigned cand = thr | (1u << b);
        int c = 0;
#pragma unroll
        for (int k = 0; k < 32; ++k) c += (pb[k] >= cand) ? 1 : 0;
        c = __reduce_add_sync(0xffffffffu, c);
        if (c >= TOPK) thr = cand;
    }

    float4* outp = reinterpret_cast<float4*>(g_sbuf + (size_t)t * D);
#pragma unroll
    for (int c = 0; c < 8; ++c) {
        float4 sv;
        sv.x = (pb[c * 4 + 0] >= thr) ? __uint_as_float(pb[c * 4 + 0]) : 0.f;
        sv.y = (pb[c * 4 + 1] >= thr) ? __uint_as_float(pb[c * 4 + 1]) : 0.f;
        sv.z = (pb[c * 4 + 2] >= thr) ? __uint_as_float(pb[c * 4 + 2]) : 0.f;
        sv.w = (pb[c * 4 + 3] >= thr) ? __uint_as_float(pb[c * 4 + 3]) : 0.f;
        outp[c * 32 + lane] = sv;
    }
}

// ---------------------------------------------------------------------------
// Kernel 2: the scan with fused expectation accumulation (proven in R2).
// Each (i,j) state entry evolves independently:
//     v <- relu(DECAY*v + s_t[i]*s_t[j]*g_t),   g_t = 1 - c_t*INHIB
// Thread owns 4 rows x 4 cols; v stays in registers across all 128 steps;
// every snapshot streams straight out with __stcs. After producing state_t,
// the block contributes s_{t+1}[i]*v[i,j] to g_expect[t+1] via atomics
// (block-uniform skip when the 4 s-rows are all zero, ~81% of steps).
// Grid: D/4 = 256 blocks x 256 threads.
// ---------------------------------------------------------------------------
__global__ void __launch_bounds__(256) scan_kernel(const float* __restrict__ con,
                                                  float* __restrict__ states) {
    const int tid = threadIdx.x;
    const int i0 = blockIdx.x * SCAN_R;
    const int j = tid * 4;

    __shared__ float4 si_sh[S];  // s_t[i0..i0+3] for all t
    __shared__ float g_sh[S];
    if (tid < S) {
        si_sh[tid] = *reinterpret_cast<const float4*>(g_sbuf + (size_t)tid * D + i0);
        g_sh[tid] = 1.0f - con[tid] * INHIB;
    }
    __syncthreads();

    float4 v[SCAN_R];
#pragma unroll
    for (int r = 0; r < SCAN_R; ++r) v[r] = make_float4(0.f, 0.f, 0.f, 0.f);

    float4 sj = __ldg(reinterpret_cast<const float4*>(g_sbuf + j));  // s_t[j..j+3]
    for (int t = 0; t < S; ++t) {
        float4 sjn = sj;
        if (t + 1 < S)
            sjn = __ldg(reinterpret_cast<const float4*>(g_sbuf + (size_t)(t + 1) * D + j));
        const float g = g_sh[t];
        const float4 si = si_sh[t];
        const float a0 = si.x * g, a1 = si.y * g, a2 = si.z * g, a3 = si.w * g;
        float* o = states + (size_t)t * D * D + j;

        v[0].x = fmaxf(fmaf(a0, sj.x, DECAY * v[0].x), 0.f);
        v[0].y = fmaxf(fmaf(a0, sj.y, DECAY * v[0].y), 0.f);
        v[0].z = fmaxf(fmaf(a0, sj.z, DECAY * v[0].z), 0.f);
        v[0].w = fmaxf(fmaf(a0, sj.w, DECAY * v[0].w), 0.f);
        v[1].x = fmaxf(fmaf(a1, sj.x, DECAY * v[1].x), 0.f);
        v[1].y = fmaxf(fmaf(a1, sj.y, DECAY * v[1].y), 0.f);
        v[1].z = fmaxf(fmaf(a1, sj.z, DECAY * v[1].z), 0.f);
        v[1].w = fmaxf(fmaf(a1, sj.w, DECAY * v[1].w), 0.f);
        v[2].x = fmaxf(fmaf(a2, sj.x, DECAY * v[2].x), 0.f);
        v[2].y = fmaxf(fmaf(a2, sj.y, DECAY * v[2].y), 0.f);
        v[2].z = fmaxf(fmaf(a2, sj.z, DECAY * v[2].z), 0.f);
        v[2].w = fmaxf(fmaf(a2, sj.w, DECAY * v[2].w), 0.f);
        v[3].x = fmaxf(fmaf(a3, sj.x, DECAY * v[3].x), 0.f);
        v[3].y = fmaxf(fmaf(a3, sj.y, DECAY * v[3].y), 0.f);
        v[3].z = fmaxf(fmaf(a3, sj.z, DECAY * v[3].z), 0.f);
        v[3].w = fmaxf(fmaf(a3, sj.w, DECAY * v[3].w), 0.f);

        __stcs(reinterpret_cast<float4*>(o + (size_t)(i0 + 0) * D), v[0]);
        __stcs(reinterpret_cast<float4*>(o + (size_t)(i0 + 1) * D), v[1]);
        __stcs(reinterpret_cast<float4*>(o + (size_t)(i0 + 2) * D), v[2]);
        __stcs(reinterpret_cast<float4*>(o + (size_t)(i0 + 3) * D), v[3]);

        // Fused expectation: contribute s_{t+1}[i0+r] * v[r][.] to expect[t+1].
        if (t + 1 < S) {
            const float4 sn = si_sh[t + 1];  // block-uniform
            if (sn.x != 0.f || sn.y != 0.f || sn.z != 0.f || sn.w != 0.f) {
                float4 cacc;
                cacc.x = sn.x * v[0].x + sn.y * v[1].x + sn.z * v[2].x + sn.w * v[3].x;
                cacc.y = sn.x * v[0].y + sn.y * v[1].y + sn.z * v[2].y + sn.w * v[3].y;
                cacc.z = sn.x * v[0].z + sn.y * v[1].z + sn.z * v[2].z + sn.w * v[3].z;
                cacc.w = sn.x * v[0].w + sn.y * v[1].w + sn.z * v[2].w + sn.w * v[3].w;
                float* e = g_expect + (size_t)(t + 1) * D + j;
                atomicAdd(e + 0, cacc.x);
                atomicAdd(e + 1, cacc.y);
                atomicAdd(e + 2, cacc.z);
                atomicAdd(e + 3, cacc.w);
            }
        }
        sj = sjn;
    }
}

// ---------------------------------------------------------------------------
// Kernel 3: finalize drifts. drift_t = ||s_t - expect_t||
// (expect_0 stays zero => drift_0 = ||s_0||).
// ---------------------------------------------------------------------------
__global__ void __launch_bounds__(256) finalize_kernel(float* __restrict__ drifts) {
    const int t = blockIdx.x;
    const int tid = threadIdx.x;
    const int lane = tid & 31, wid = tid >> 5;

    float4 s4 = reinterpret_cast<const float4*>(g_sbuf + (size_t)t * D)[tid];
    float4 e4 = reinterpret_cast<const float4*>(g_expect + (size_t)t * D)[tid];
    const float dx = s4.x - e4.x, dy = s4.y - e4.y;
    const float dz = s4.z - e4.z, dw = s4.w - e4.w;
    float sum = dx * dx + dy * dy + dz * dz + dw * dw;
#pragma unroll
    for (int o = 16; o > 0; o >>= 1) sum += __shfl_xor_sync(0xffffffffu, sum, o);

    __shared__ float ws[8];
    if (lane == 0) ws[wid] = sum;
    __syncthreads();
    if (tid == 0) {
        float tot = 0.f;
        for (int w = 0; w < 8; ++w) tot += ws[w];
        drifts[t] = sqrtf(tot);
    }
}

// ---------------------------------------------------------------------------
extern "C" void kernel_launch(void* const* d_in, const int* in_sizes, int n_in,
                              void* d_out, int out_size) {
    const float* emb;
    const float* con;
    if (in_sizes[0] == S) {
        con = (const float*)d_in[0];
        emb = (const float*)d_in[1];
    } else {
        emb = (const float*)d_in[0];
        con = (const float*)d_in[1];
    }
    float* out = (float*)d_out;
    float* drifts = out;      // [S]
    float* states = out + S;  // [S, D, D]

    sparsify_kernel<<<16, 256>>>(emb);
    scan_kernel<<<D / SCAN_R, 256>>>(con, states);
    finalize_kernel<<<S, 256>>>(drifts);
}

// round 7
// speedup vs baseline: 1.2895x; 1.0420x over previous
#include <cuda_runtime.h>
#include <math.h>

#define D 1024
#define S 128
#define DECAY 0.99f
#define INHIB 1.5f
#define TOPK 51
#define SCAN_R 4

// Scratch (static device globals — no allocation).
__device__ float g_sbuf[S * D];    // sparsified token vectors [S][D]
__device__ float g_expect[S * D];  // expectation_t[j] accumulated by scan atomics

// ---------------------------------------------------------------------------
// Kernel 1: sparsify. 128 blocks x 64 threads (proven best spread: one radix
// warp per SM). Warp 0: exact 2-bit radix top-k select for token bid.
// Warp 1: zero g_expect row bid.
// Exactness: nonneg-float order == uint order. 2-bit step: pick the largest
// digit d in {3,2,1,0} with count(x >= thr | d<<b) >= TOPK. The three
// cumulative counts are packed in 11-bit fields of one uint and summed with a
// single __reduce_add_sync (fields can't overflow: every count <= #positives
// <= 1023, since relu zeros never pass any candidate >= 2).
// ---------------------------------------------------------------------------
__global__ void __launch_bounds__(64) sparsify_kernel(const float* __restrict__ emb) {
    const int t = blockIdx.x;
    const int lane = threadIdx.x & 31;

    if (threadIdx.x >= 32) {  // warp 1: zero g_expect row t
        float4 z = make_float4(0.f, 0.f, 0.f, 0.f);
        float4* e4 = reinterpret_cast<float4*>(g_expect + (size_t)t * D);
#pragma unroll
        for (int c = 0; c < 8; ++c) e4[c * 32 + lane] = z;
        return;
    }

    // warp 0: load relu(x) as raw bits, 32 values per lane, coalesced
    unsigned pb[32];
    const float4* row = reinterpret_cast<const float4*>(emb + (size_t)t * D);
#pragma unroll
    for (int c = 0; c < 8; ++c) {
        float4 x = row[c * 32 + lane];
        pb[c * 4 + 0] = __float_as_uint(fmaxf(x.x, 0.f));
        pb[c * 4 + 1] = __float_as_uint(fmaxf(x.y, 0.f));
        pb[c * 4 + 2] = __float_as_uint(fmaxf(x.z, 0.f));
        pb[c * 4 + 3] = __float_as_uint(fmaxf(x.w, 0.f));
    }

    unsigned thr = 0u;
    // 2 bits per iteration: pairs (30,29),(28,27),...,(2,1)
#pragma unroll 1
    for (int b = 29; b >= 1; b -= 2) {
        const unsigned t1 = thr | (1u << b);
        const unsigned t2 = thr | (2u << b);
        const unsigned t3 = thr | (3u << b);
        unsigned p = 0;
#pragma unroll
        for (int k = 0; k < 32; ++k) {
            const unsigned x = pb[k];
            p += (x >= t3) ? 1u : 0u;
            p += (x >= t2) ? (1u << 11) : 0u;
            p += (x >= t1) ? (1u << 22) : 0u;
        }
        p = __reduce_add_sync(0xffffffffu, p);
        const unsigned n3 = p & 0x7FFu;          // count >= t3
        const unsigned n2 = (p >> 11) & 0x7FFu;  // count >= t2 (cumulative)
        const unsigned n1 = p >> 22;             // count >= t1 (cumulative)
        if (n3 >= TOPK)      thr = t3;
        else if (n2 >= TOPK) thr = t2;
        else if (n1 >= TOPK) thr = t1;
    }
    {   // final bit 0
        const unsigned cand = thr | 1u;
        int c = 0;
#pragma unroll
        for (int k = 0; k < 32; ++k) c += (pb[k] >= cand) ? 1 : 0;
        c = __reduce_add_sync(0xffffffffu, c);
        if (c >= TOPK) thr = cand;
    }

    float4* outp = reinterpret_cast<float4*>(g_sbuf + (size_t)t * D);
#pragma unroll
    for (int c = 0; c < 8; ++c) {
        float4 sv;
        sv.x = (pb[c * 4 + 0] >= thr) ? __uint_as_float(pb[c * 4 + 0]) : 0.f;
        sv.y = (pb[c * 4 + 1] >= thr) ? __uint_as_float(pb[c * 4 + 1]) : 0.f;
        sv.z = (pb[c * 4 + 2] >= thr) ? __uint_as_float(pb[c * 4 + 2]) : 0.f;
        sv.w = (pb[c * 4 + 3] >= thr) ? __uint_as_float(pb[c * 4 + 3]) : 0.f;
        outp[c * 32 + lane] = sv;
    }
}

// ---------------------------------------------------------------------------
// Kernel 2: the scan with fused expectation accumulation (proven; unchanged
// except the PDL grid-dependency sync at entry).
//     v <- relu(DECAY*v + s_t[i]*s_t[j]*g_t),   g_t = 1 - c_t*INHIB
// Thread owns 4 rows x 4 cols; v register-resident across all 128 steps;
// snapshots stream out with __stcs. s_{t+1}[i]*v -> g_expect[t+1] atomics
// (block-uniform skip when all 4 s-rows are zero, ~81% of steps).
// ---------------------------------------------------------------------------
__global__ void __launch_bounds__(256) scan_kernel(const float* __restrict__ con,
                                                  float* __restrict__ states) {
    cudaGridDependencySynchronize();  // PDL: wait for sparsify completion

    const int tid = threadIdx.x;
    const int i0 = blockIdx.x * SCAN_R;
    const int j = tid * 4;

    __shared__ float4 si_sh[S];  // s_t[i0..i0+3] for all t
    __shared__ float g_sh[S];
    if (tid < S) {
        si_sh[tid] = *reinterpret_cast<const float4*>(g_sbuf + (size_t)tid * D + i0);
        g_sh[tid] = 1.0f - con[tid] * INHIB;
    }
    __syncthreads();

    float4 v[SCAN_R];
#pragma unroll
    for (int r = 0; r < SCAN_R; ++r) v[r] = make_float4(0.f, 0.f, 0.f, 0.f);

    float4 sj = __ldg(reinterpret_cast<const float4*>(g_sbuf + j));  // s_t[j..j+3]
    for (int t = 0; t < S; ++t) {
        float4 sjn = sj;
        if (t + 1 < S)
            sjn = __ldg(reinterpret_cast<const float4*>(g_sbuf + (size_t)(t + 1) * D + j));
        const float g = g_sh[t];
        const float4 si = si_sh[t];
        const float a0 = si.x * g, a1 = si.y * g, a2 = si.z * g, a3 = si.w * g;
        float* o = states + (size_t)t * D * D + j;

        v[0].x = fmaxf(fmaf(a0, sj.x, DECAY * v[0].x), 0.f);
        v[0].y = fmaxf(fmaf(a0, sj.y, DECAY * v[0].y), 0.f);
        v[0].z = fmaxf(fmaf(a0, sj.z, DECAY * v[0].z), 0.f);
        v[0].w = fmaxf(fmaf(a0, sj.w, DECAY * v[0].w), 0.f);
        v[1].x = fmaxf(fmaf(a1, sj.x, DECAY * v[1].x), 0.f);
        v[1].y = fmaxf(fmaf(a1, sj.y, DECAY * v[1].y), 0.f);
        v[1].z = fmaxf(fmaf(a1, sj.z, DECAY * v[1].z), 0.f);
        v[1].w = fmaxf(fmaf(a1, sj.w, DECAY * v[1].w), 0.f);
        v[2].x = fmaxf(fmaf(a2, sj.x, DECAY * v[2].x), 0.f);
        v[2].y = fmaxf(fmaf(a2, sj.y, DECAY * v[2].y), 0.f);
        v[2].z = fmaxf(fmaf(a2, sj.z, DECAY * v[2].z), 0.f);
        v[2].w = fmaxf(fmaf(a2, sj.w, DECAY * v[2].w), 0.f);
        v[3].x = fmaxf(fmaf(a3, sj.x, DECAY * v[3].x), 0.f);
        v[3].y = fmaxf(fmaf(a3, sj.y, DECAY * v[3].y), 0.f);
        v[3].z = fmaxf(fmaf(a3, sj.z, DECAY * v[3].z), 0.f);
        v[3].w = fmaxf(fmaf(a3, sj.w, DECAY * v[3].w), 0.f);

        __stcs(reinterpret_cast<float4*>(o + (size_t)(i0 + 0) * D), v[0]);
        __stcs(reinterpret_cast<float4*>(o + (size_t)(i0 + 1) * D), v[1]);
        __stcs(reinterpret_cast<float4*>(o + (size_t)(i0 + 2) * D), v[2]);
        __stcs(reinterpret_cast<float4*>(o + (size_t)(i0 + 3) * D), v[3]);

        if (t + 1 < S) {
            const float4 sn = si_sh[t + 1];  // block-uniform
            if (sn.x != 0.f || sn.y != 0.f || sn.z != 0.f || sn.w != 0.f) {
                float4 cacc;
                cacc.x = sn.x * v[0].x + sn.y * v[1].x + sn.z * v[2].x + sn.w * v[3].x;
                cacc.y = sn.x * v[0].y + sn.y * v[1].y + sn.z * v[2].y + sn.w * v[3].y;
                cacc.z = sn.x * v[0].z + sn.y * v[1].z + sn.z * v[2].z + sn.w * v[3].z;
                cacc.w = sn.x * v[0].w + sn.y * v[1].w + sn.z * v[2].w + sn.w * v[3].w;
                float* e = g_expect + (size_t)(t + 1) * D + j;
                atomicAdd(e + 0, cacc.x);
                atomicAdd(e + 1, cacc.y);
                atomicAdd(e + 2, cacc.z);
                atomicAdd(e + 3, cacc.w);
            }
        }
        sj = sjn;
    }
}

// ---------------------------------------------------------------------------
// Kernel 3: finalize. drift_t = ||s_t - expect_t|| (expect_0 = 0 => ||s_0||).
// ---------------------------------------------------------------------------
__global__ void __launch_bounds__(256) finalize_kernel(float* __restrict__ drifts) {
    cudaGridDependencySynchronize();  // PDL: wait for scan completion

    const int t = blockIdx.x;
    const int tid = threadIdx.x;
    const int lane = tid & 31, wid = tid >> 5;

    float4 s4 = reinterpret_cast<const float4*>(g_sbuf + (size_t)t * D)[tid];
    float4 e4 = reinterpret_cast<const float4*>(g_expect + (size_t)t * D)[tid];
    const float dx = s4.x - e4.x, dy = s4.y - e4.y;
    const float dz = s4.z - e4.z, dw = s4.w - e4.w;
    float sum = dx * dx + dy * dy + dz * dz + dw * dw;
#pragma unroll
    for (int o = 16; o > 0; o >>= 1) sum += __shfl_xor_sync(0xffffffffu, sum, o);

    __shared__ float ws[8];
    if (lane == 0) ws[wid] = sum;
    __syncthreads();
    if (tid == 0) {
        float tot = 0.f;
        for (int w = 0; w < 8; ++w) tot += ws[w];
        drifts[t] = sqrtf(tot);
    }
}

// ---------------------------------------------------------------------------
extern "C" void kernel_launch(void* const* d_in, const int* in_sizes, int n_in,
                              void* d_out, int out_size) {
    const float* emb;
    const float* con;
    if (in_sizes[0] == S) {
        con = (const float*)d_in[0];
        emb = (const float*)d_in[1];
    } else {
        emb = (const float*)d_in[0];
        con = (const float*)d_in[1];
    }
    float* out = (float*)d_out;
    float* drifts = out;      // [S]
    float* states = out + S;  // [S, D, D]

    sparsify_kernel<<<S, 64>>>(emb);

    // Scan + finalize with programmatic stream serialization (PDL): the
    // dependent kernel may be launched while the predecessor drains; the
    // cudaGridDependencySynchronize() at kernel entry enforces correctness.
    cudaLaunchAttribute attr[1];
    attr[0].id = cudaLaunchAttributeProgrammaticStreamSerialization;
    attr[0].val.programmaticStreamSerializationAllowed = 1;

    {
        cudaLaunchConfig_t cfg = {};
        cfg.gridDim = dim3(D / SCAN_R);
        cfg.blockDim = dim3(256);
        cfg.dynamicSmemBytes = 0;
        cfg.stream = (cudaStream_t)0;
        cfg.attrs = attr;
        cfg.numAttrs = 1;
        cudaLaunchKernelEx(&cfg, scan_kernel, con, states);
    }
    {
        cudaLaunchConfig_t cfg = {};
        cfg.gridDim = dim3(S);
        cfg.blockDim = dim3(256);
        cfg.dynamicSmemBytes = 0;
        cfg.stream = (cudaStream_t)0;
        cfg.attrs = attr;
        cfg.numAttrs = 1;
        cudaLaunchKernelEx(&cfg, finalize_kernel, drifts);
    }
}